// round 9
// baseline (speedup 1.0000x reference)
#include <cuda_runtime.h>
#include <cstdint>

#define BB 8
#define CC 16
#define NND 512
#define EE 1024
#define PLANE (NND * NND)              // 262144
#define NPOS (BB * PLANE)              // 2,097,152
#define TPOS 256                       // positions per tile
#define TOTAL_TILES (NPOS / TPOS)      // 8192
#define G 296                          // persistent CTAs = 2 per SM
#define STAGES 6
#define STAGE_BYTES (TPOS * CC * 4)    // 16384
#define THREADS 256

// Shared memory layout (dynamic)
#define SM_ADJ   0                                   // 6 x 16384 = 98304
#define SM_LAB   (STAGES * STAGE_BYTES)              // 98304  (int[256])
#define SM_MBAR  (SM_LAB + 1024)                     // 99328  (6 x 8)
#define SM_FLAGS (SM_MBAR + 64)                      // 99392  (int[2])
#define SM_ACCS  (SM_FLAGS + 8)                      // 99400  (float[8])
#define SM_ACCC  (SM_ACCS + 32)                      // 99432  (float[8])
#define SM_BAT   (SM_ACCC + 32)                      // 99464  (double[8], 8B aligned)
#define SM_TOTAL (SM_BAT + 64)                       // 99528

// Globals: overwrite-only partials + monotonic done counter (no zeroing needed).
__device__ float2 g_part[G * BB];
__device__ unsigned int g_done;

__device__ __forceinline__ uint32_t smem_u32(const void* p) {
    uint32_t a;
    asm("{ .reg .u64 t; cvta.to.shared.u64 t, %1; cvt.u32.u64 %0, t; }"
        : "=r"(a) : "l"(p));
    return a;
}

__device__ __forceinline__ void mbar_wait(uint32_t mbar, uint32_t parity) {
    asm volatile(
        "{\n\t"
        ".reg .pred P;\n\t"
        "LAB_WAIT_%=:\n\t"
        "mbarrier.try_wait.parity.acquire.cta.shared::cta.b64 P, [%0], %1, 0x989680;\n\t"
        "@P bra.uni LAB_DONE_%=;\n\t"
        "bra.uni LAB_WAIT_%=;\n\t"
        "LAB_DONE_%=:\n\t"
        "}"
        :: "r"(mbar), "r"(parity) : "memory");
}

// Fill stage `st` with tile `tl`: expect_tx + 16 class copies of 1KB each.
#define ISSUE_FILL(st, tl) do {                                                   \
    uint32_t _mb = mbar_base + (st) * 8;                                          \
    asm volatile("mbarrier.arrive.expect_tx.shared.b64 _, [%0], %1;"              \
                 :: "r"(_mb), "r"(STAGE_BYTES) : "memory");                       \
    const float* _src = adj + (size_t)((tl) >> 10) * (CC * PLANE)                 \
                            + (((tl) & 1023) << 8);                               \
    uint32_t _dst = smem_base + SM_ADJ + (st) * STAGE_BYTES;                      \
    _Pragma("unroll")                                                             \
    for (int _c = 0; _c < CC; _c++) {                                             \
        asm volatile(                                                             \
            "cp.async.bulk.shared::cluster.global.mbarrier::complete_tx::bytes "  \
            "[%0], [%1], %2, [%3];"                                               \
            :: "r"(_dst + _c * (TPOS * 4)), "l"(_src + (size_t)_c * PLANE),       \
               "r"(TPOS * 4), "r"(_mb) : "memory");                               \
    }                                                                             \
} while (0)

// ---------------------------------------------------------------------------
// Persistent fused kernel: 6-stage bulk-async pipeline over 256-position
// tiles; per-tile smem edge scatter; masked CE; overwrite-only partials.
// ---------------------------------------------------------------------------
__global__ void __launch_bounds__(THREADS) fused_kernel(
    const float* __restrict__ adj, const unsigned char* __restrict__ mask,
    const int* __restrict__ ei, const int* __restrict__ ea,
    float* __restrict__ out) {

    extern __shared__ char smem[];
    int*    s_lab   = (int*)(smem + SM_LAB);
    int*    s_flags = (int*)(smem + SM_FLAGS);
    float*  s_accs  = (float*)(smem + SM_ACCS);
    float*  s_accc  = (float*)(smem + SM_ACCC);
    double* s_bat   = (double*)(smem + SM_BAT);
    const uint32_t smem_base = smem_u32(smem);
    const uint32_t mbar_base = smem_base + SM_MBAR;

    const int tid  = threadIdx.x;
    const int bid  = blockIdx.x;
    const int lane = tid & 31;
    const int w    = tid >> 5;

    // ---- init: barriers, flags, accumulators
    if (tid == 0) {
#pragma unroll
        for (int s = 0; s < STAGES; s++)
            asm volatile("mbarrier.init.shared.b64 [%0], %1;"
                         :: "r"(mbar_base + s * 8), "r"(1) : "memory");
        asm volatile("fence.proxy.async.shared::cta;" ::: "memory");
    }
    if (tid < 2) s_flags[tid] = 0;
    if (tid < BB) { s_accs[tid] = 0.f; s_accc[tid] = 0.f; }
    __syncthreads();

    // ---- mask dtype detection from mask[0..1024) bytes
    //   u8 bool: nonzero at off%4==1; f32 1.0f: only %4==2,3; i32: only %4==0
    {
        uchar4 mv = ((const uchar4*)mask)[tid];
        if (mv.y) atomicOr(&s_flags[0], 1);
        if (mv.z | mv.w) atomicOr(&s_flags[1], 1);
    }
    __syncthreads();
    const int mode = s_flags[0] ? 0 : (s_flags[1] ? 2 : 1);

    // ---- prologue: fill the ring
    if (tid == 0) {
#pragma unroll
        for (int s = 0; s < STAGES; s++) {
            int t = bid + s * G;
            if (t < TOTAL_TILES) ISSUE_FILL(s, t);
        }
    }

    // ---- main pipelined loop
    int st = 0, ph = 0;
    for (int t = bid; t < TOTAL_TILES; t += G) {
        const int b = t >> 10;               // 1024 tiles per batch
        const int r = (t & 1023) << 8;       // position offset in plane

        // zero label tile
        s_lab[tid] = 0;
        __syncthreads();

        // scatter this batch's edges (highest e wins, deterministic)
        const int base = b << 10;
#pragma unroll
        for (int k = 0; k < 4; k++) {
            int e = tid + (k << 8);
            int2 ij = ((const int2*)ei)[base + e];
            int a   = ea[base + e];
            int pos = ij.x * NND + ij.y - r;
            if ((unsigned)pos < (unsigned)TPOS)
                atomicMax(&s_lab[pos], (e << 5) | a);
        }

        // mask value for my position (overlaps scatter/fill)
        const int p = b * PLANE + r + tid;
        float mv;
        if (mode == 0)      mv = mask[p] ? 1.f : 0.f;
        else if (mode == 1) mv = ((const int*)mask)[p] ? 1.f : 0.f;
        else                mv = (((const float*)mask)[p] != 0.f) ? 1.f : 0.f;

        __syncthreads();
        const int lab = s_lab[tid] & 31;

        // wait for this stage's adj data
        mbar_wait(mbar_base + st * 8, ph);

        // compute CE from smem (conflict-free scalar LDS)
        const float* sa = (const float*)(smem + SM_ADJ + st * STAGE_BYTES);
        float sacc = 0.f, pick = 0.f;
#pragma unroll
        for (int c = 0; c < CC; c++) {
            float x = sa[c * TPOS + tid];
            sacc += __expf(x);
            pick = (c == lab) ? x : pick;
        }
        float lsum = mv * (__logf(sacc) - pick);
        float lcnt = mv;

        // warp reduce -> per-batch smem accumulators
#pragma unroll
        for (int off = 16; off > 0; off >>= 1) {
            lsum += __shfl_down_sync(0xFFFFFFFFu, lsum, off);
            lcnt += __shfl_down_sync(0xFFFFFFFFu, lcnt, off);
        }
        if (lane == 0) {
            atomicAdd(&s_accs[b], lsum);
            atomicAdd(&s_accc[b], lcnt);
        }

        __syncthreads();                     // stage + s_lab fully consumed

        // refill this stage with the tile STAGES ahead
        int tn = t + STAGES * G;
        if (tid == 0 && tn < TOTAL_TILES) ISSUE_FILL(st, tn);

        if (++st == STAGES) { st = 0; ph ^= 1; }
    }

    // ---- publish per-CTA partials, elect last CTA
    __syncthreads();
    if (tid < BB)
        g_part[bid * BB + tid] = make_float2(s_accs[tid], s_accc[tid]);
    __threadfence();
    __syncthreads();
    if (tid == 0) {
        unsigned int old = atomicAdd(&g_done, 1u);
        s_flags[0] = ((old % (unsigned)G) == (unsigned)(G - 1)) ? 2 : 3;
    }
    __syncthreads();

    // ---- last CTA: final reduction (warp w handles batch w)
    if (s_flags[0] == 2) {
        __threadfence();
        double ds = 0.0, dc = 0.0;
        for (int i = lane; i < G; i += 32) {
            float2 pr = __ldcg(&g_part[i * BB + w]);
            ds += (double)pr.x;
            dc += (double)pr.y;
        }
#pragma unroll
        for (int off = 16; off > 0; off >>= 1) {
            ds += __shfl_down_sync(0xFFFFFFFFu, ds, off);
            dc += __shfl_down_sync(0xFFFFFFFFu, dc, off);
        }
        if (lane == 0) {
            if (dc < 1.0) dc = 1.0;
            s_bat[w] = ds / dc;
        }
        __syncthreads();
        if (tid == 0) {
            double acc = 0.0;
#pragma unroll
            for (int i = 0; i < BB; i++) acc += s_bat[i];
            out[0] = (float)(acc / (double)BB);
        }
    }
}

// ---------------------------------------------------------------------------
extern "C" void kernel_launch(void* const* d_in, const int* in_sizes, int n_in,
                              void* d_out, int out_size) {
    const float*         adj  = (const float*)d_in[0];
    const unsigned char* mask = (const unsigned char*)d_in[1];
    const int*           ei   = (const int*)d_in[2];
    const int*           ea   = (const int*)d_in[3];

    cudaFuncSetAttribute(fused_kernel,
                         cudaFuncAttributeMaxDynamicSharedMemorySize, SM_TOTAL);
    fused_kernel<<<G, THREADS, SM_TOTAL>>>(adj, mask, ei, ea, (float*)d_out);
}

// round 10
// speedup vs baseline: 1.9928x; 1.9928x over previous
#include <cuda_runtime.h>
#include <cstdint>

#define BB 8
#define CC 16
#define NND 512
#define EE 1024
#define PLANE (NND * NND)            // 262144
#define NPOS (BB * PLANE)            // 2,097,152
#define CHUNK 1024                   // positions per CTA
#define NCTA (NPOS / CHUNK)          // 2048
#define THREADS 256

// Globals: overwrite-only partials + monotonic done counter (never zeroed;
// same inputs -> same values every call, last-CTA election via mod NCTA).
__device__ float2 g_part[NCTA];
__device__ unsigned int g_done;

// ---------------------------------------------------------------------------
// One fused kernel. Each CTA: scatter its batch's edges into a 1024-slot smem
// label tile (overlapping the first adj loads), detect mask dtype, then the
// R5-proven direct-LDG on-the-fly CE loop (4 positions/thread, float4).
// ---------------------------------------------------------------------------
__global__ void __launch_bounds__(THREADS, 4) fused_kernel(
    const float* __restrict__ adj, const unsigned char* __restrict__ mask,
    const int* __restrict__ ei, const int* __restrict__ ea,
    float* __restrict__ out) {

    __shared__ int    s_lab[CHUNK];
    __shared__ int    s_flags[2];
    __shared__ float  s_wred[16];          // wsum[8], wcnt[8]
    __shared__ double s_bat[BB];
    __shared__ int    s_role;

    const int tid  = threadIdx.x;
    const int bid  = blockIdx.x;
    const int lane = tid & 31;
    const int w    = tid >> 5;
    const int b    = bid >> 8;             // 256 CTAs per batch
    const int r    = (bid & 255) << 10;    // chunk start within N*N plane

    // ---- init label tile + flags
    ((int4*)s_lab)[tid] = make_int4(0, 0, 0, 0);
    if (tid < 2) s_flags[tid] = 0;
    __syncthreads();

    // ---- scatter this batch's edges (highest e wins, deterministic)
    {
        const int base = b << 10;          // EE = 1024
#pragma unroll
        for (int k = 0; k < 4; k++) {
            int e = tid + (k << 8);
            int2 ij = ((const int2*)ei)[base + e];
            int a   = ea[base + e];
            int pos = ij.x * NND + ij.y - r;
            if ((unsigned)pos < (unsigned)CHUNK)
                atomicMax(&s_lab[pos], (e << 5) | a);
        }
    }

    // ---- mask dtype detection from mask[0..1024) bytes (L2-hot)
    //   u8 bool: nonzero at off%4==1; f32 1.0f: only %4==2,3; i32: only %4==0
    {
        uchar4 mv = ((const uchar4*)mask)[tid];
        if (mv.y) atomicOr(&s_flags[0], 1);
        if (mv.z | mv.w) atomicOr(&s_flags[1], 1);
    }
    __syncthreads();

    const int mode = s_flags[0] ? 0 : (s_flags[1] ? 2 : 1);
    const int p = b * PLANE + r + tid * 4;            // my global position
    const float* adjb = adj + (size_t)b * CC * PLANE + r + tid * 4;

    // ---- mask values (uniform branch on mode)
    float v0, v1, v2, v3;
    if (mode == 0) {
        uchar4 mm = ((const uchar4*)mask)[p >> 2];
        v0 = mm.x ? 1.f : 0.f; v1 = mm.y ? 1.f : 0.f;
        v2 = mm.z ? 1.f : 0.f; v3 = mm.w ? 1.f : 0.f;
    } else if (mode == 1) {
        int4 mm = ((const int4*)mask)[p >> 2];
        v0 = mm.x ? 1.f : 0.f; v1 = mm.y ? 1.f : 0.f;
        v2 = mm.z ? 1.f : 0.f; v3 = mm.w ? 1.f : 0.f;
    } else {
        float4 mm = ((const float4*)mask)[p >> 2];
        v0 = (mm.x != 0.f) ? 1.f : 0.f; v1 = (mm.y != 0.f) ? 1.f : 0.f;
        v2 = (mm.z != 0.f) ? 1.f : 0.f; v3 = (mm.w != 0.f) ? 1.f : 0.f;
    }

    // ---- labels for my 4 positions
    int4 lv = ((const int4*)s_lab)[tid];
    const int lab0 = lv.x & 31, lab1 = lv.y & 31,
              lab2 = lv.z & 31, lab3 = lv.w & 31;

    // ---- stream 16 classes from DRAM; consume on the fly (small live set)
    float sx = 0.f, sy = 0.f, sz = 0.f, sw = 0.f;
    float p0 = 0.f, p1 = 0.f, p2 = 0.f, p3 = 0.f;
#pragma unroll
    for (int c = 0; c < CC; c++) {
        float4 xc = *(const float4*)(adjb + (size_t)c * PLANE);
        sx += __expf(xc.x);
        sy += __expf(xc.y);
        sz += __expf(xc.z);
        sw += __expf(xc.w);
        p0 = (c == lab0) ? xc.x : p0;
        p1 = (c == lab1) ? xc.y : p1;
        p2 = (c == lab2) ? xc.z : p2;
        p3 = (c == lab3) ? xc.w : p3;
    }

    float lsum = v0 * (__logf(sx) - p0) + v1 * (__logf(sy) - p1)
               + v2 * (__logf(sz) - p2) + v3 * (__logf(sw) - p3);
    float lcnt = v0 + v1 + v2 + v3;

    // ---- block reduce (warp shuffle + 8-slot shared)
#pragma unroll
    for (int off = 16; off > 0; off >>= 1) {
        lsum += __shfl_down_sync(0xFFFFFFFFu, lsum, off);
        lcnt += __shfl_down_sync(0xFFFFFFFFu, lcnt, off);
    }
    if (lane == 0) { s_wred[w] = lsum; s_wred[8 + w] = lcnt; }
    __syncthreads();

    if (tid == 0) {
        float bs = 0.f, bc = 0.f;
#pragma unroll
        for (int i = 0; i < 8; i++) { bs += s_wred[i]; bc += s_wred[8 + i]; }
        g_part[bid] = make_float2(bs, bc);
        __threadfence();
        unsigned int old = atomicAdd(&g_done, 1u);
        s_role = ((old & (NCTA - 1)) == (NCTA - 1)) ? 1 : 0;
    }
    __syncthreads();

    // ---- last CTA: reduce 2048 partials; warp w == batch w (256 slots each)
    if (s_role == 1) {
        __threadfence();
        double ds = 0.0, dc = 0.0;
        const int slot0 = (w << 8) + lane * 8;
#pragma unroll
        for (int k = 0; k < 8; k++) {
            float2 pr = __ldcg(&g_part[slot0 + k]);
            ds += (double)pr.x;
            dc += (double)pr.y;
        }
#pragma unroll
        for (int off = 16; off > 0; off >>= 1) {
            ds += __shfl_down_sync(0xFFFFFFFFu, ds, off);
            dc += __shfl_down_sync(0xFFFFFFFFu, dc, off);
        }
        if (lane == 0) {
            if (dc < 1.0) dc = 1.0;
            s_bat[w] = ds / dc;
        }
        __syncthreads();
        if (tid == 0) {
            double acc = 0.0;
#pragma unroll
            for (int i = 0; i < BB; i++) acc += s_bat[i];
            out[0] = (float)(acc / (double)BB);
        }
    }
}

// ---------------------------------------------------------------------------
extern "C" void kernel_launch(void* const* d_in, const int* in_sizes, int n_in,
                              void* d_out, int out_size) {
    const float*         adj  = (const float*)d_in[0];
    const unsigned char* mask = (const unsigned char*)d_in[1];
    const int*           ei   = (const int*)d_in[2];
    const int*           ea   = (const int*)d_in[3];

    fused_kernel<<<NCTA, THREADS>>>(adj, mask, ei, ea, (float*)d_out);
}